// round 16
// baseline (speedup 1.0000x reference)
#include <cuda_runtime.h>
#include <cuda_bf16.h>
#include <cuda_fp16.h>
#include <cstdint>

#define Hd 1024
#define Vv 32000
#define Bb 64
#define Ss 64
#define Tt 13
#define SOS_TOK 2
#define NB5 5120   // W_hh rows (4096) + Wa rows (1024)

// ---------------- static scratch ------------------------------------------
__device__ float g_h[Bb * Hd];
__device__ float g_c[Bb * Hd];
__device__ float g_hp[4][Bb * NB5];          // h@[W_hh|Wa]^T partials (4 k-slices)
__device__ float g_cp[4][Bb * 4096];         // ctx@W_ihc^T partials
__device__ float g_xpre[896 * 4096];         // x@W_ihx^T + b_ih + b_hh (all steps)

__device__ __half g_keysH[Bb * Ss * Hd];     // keys_proj (fp16)
__device__ __half g_hH[Bb * Hd];             // h (fp16)
__device__ __half g_ctxH[Bb * Hd];           // ctx (fp16)
__device__ __half g_encH[Bb * Ss * Hd];      // enc (fp16)
__device__ __half g_UaH[Hd * Hd];
__device__ __half g_BhH[NB5 * Hd];           // [W_hh;Wa]
__device__ __half g_WxH[4096 * Hd];          // W_ih x-cols
__device__ __half g_WcH[4096 * Hd];          // W_ih ctx-cols
__device__ __half g_xgH[896 * Hd];           // gathered emb
__device__ __nv_bfloat16 g_nhb[896 * Hd];
__device__ __nv_bfloat16 g_outWb[(size_t)Vv * Hd];

// ---------------- math helpers -------------------------------------------
__device__ __forceinline__ float rcp_fast(float d) {
    float r = __int_as_float(0x7EF311C3 - __float_as_int(d));
    r = r * __fmaf_rn(-d, r, 2.0f);
    r = r * __fmaf_rn(-d, r, 2.0f);
    return r;
}
__device__ __forceinline__ float tanh_mufu(float x) {
    float y;
    asm("tanh.approx.f32 %0, %1;" : "=f"(y) : "f"(x));
    return y;
}
__device__ __forceinline__ float tanh_poly(float x) {
    float cx = fminf(fmaxf(x, -4.97f), 4.97f);
    float t = cx * cx;
    float p = t + 378.f;
    p = __fmaf_rn(p, t, 17325.f);
    p = __fmaf_rn(p, t, 135135.f);
    p = p * cx;
    float q = __fmaf_rn(28.f, t, 3150.f);
    q = __fmaf_rn(q, t, 62370.f);
    q = __fmaf_rn(q, t, 135135.f);
    return p * rcp_fast(q);
}
__device__ __forceinline__ float sigmoid_fast(float x) {
    return rcp_fast(1.f + __expf(-x));
}

// ---------------- mma helpers --------------------------------------------
__device__ __forceinline__ void mma16816bf(float* d, const uint32_t* a, const uint32_t* b) {
    asm volatile(
        "mma.sync.aligned.m16n8k16.row.col.f32.bf16.bf16.f32 "
        "{%0,%1,%2,%3}, {%4,%5,%6,%7}, {%8,%9}, {%0,%1,%2,%3};\n"
        : "+f"(d[0]), "+f"(d[1]), "+f"(d[2]), "+f"(d[3])
        : "r"(a[0]), "r"(a[1]), "r"(a[2]), "r"(a[3]), "r"(b[0]), "r"(b[1]));
}
__device__ __forceinline__ void mma16816h(float* d, const uint32_t* a, const uint32_t* b) {
    asm volatile(
        "mma.sync.aligned.m16n8k16.row.col.f32.f16.f16.f32 "
        "{%0,%1,%2,%3}, {%4,%5,%6,%7}, {%8,%9}, {%0,%1,%2,%3};\n"
        : "+f"(d[0]), "+f"(d[1]), "+f"(d[2]), "+f"(d[3])
        : "r"(a[0]), "r"(a[1]), "r"(a[2]), "r"(a[3]), "r"(b[0]), "r"(b[1]));
}

// ===== 64m x 64n fp16 GEMM body, 128 thr, variable K window ==============
// HOUT=false: fp32 out (+opt bias). HOUT=true: fp16 out (+opt bias).
template<bool HOUT>
__device__ __forceinline__ void gemm64x64h(
    const __half* __restrict__ Ah, const __half* __restrict__ Bh,
    int kb0, int kw, void* __restrict__ outp, int ocol0, int ostride,
    const float* __restrict__ bias1, const float* __restrict__ bias2,
    __half* smp)
{
    const int K = Hd;
    const int tid = threadIdx.x;
    const int wid = tid >> 5, lane = tid & 31;
    const int g = lane >> 2, tg = lane & 3;
    const int qm = lane >> 3, lr = lane & 7;
    const uint32_t smb = (uint32_t)__cvta_generic_to_shared(smp);

    float acc[4][2][4];
#pragma unroll
    for (int a = 0; a < 4; a++)
#pragma unroll
        for (int b = 0; b < 2; b++)
#pragma unroll
            for (int c = 0; c < 4; c++) acc[a][b][c] = 0.f;

#define GH_LOAD(st, k0)                                                             \
    {                                                                               \
        _Pragma("unroll")                                                           \
        for (int rep = 0; rep < 2; ++rep) {                                         \
            int idx = tid + rep * 128;                                              \
            int row = idx >> 2, c8 = (idx & 3) * 8;                                 \
            uint32_t d0 = smb + (uint32_t)((st) * 10240 + row * 80 + c8 * 2);       \
            asm volatile("cp.async.cg.shared.global [%0], [%1], 16;\n"              \
                         ::"r"(d0), "l"(Ah + (size_t)row * K + (k0) + c8));         \
            asm volatile("cp.async.cg.shared.global [%0], [%1], 16;\n"              \
                         ::"r"(d0 + 5120), "l"(Bh + (size_t)row * K + (k0) + c8));  \
        }                                                                           \
    }

    GH_LOAD(0, kb0)
    asm volatile("cp.async.commit_group;\n" ::: "memory");

    int cur = 0;
#pragma unroll 1
    for (int k0 = kb0; k0 < kb0 + kw; k0 += 32) {
        asm volatile("cp.async.wait_group 0;\n" ::: "memory");
        __syncthreads();
        if (k0 + 32 < kb0 + kw) {
            GH_LOAD(cur ^ 1, k0 + 32)
            asm volatile("cp.async.commit_group;\n" ::: "memory");
        }

#pragma unroll
        for (int ki = 0; ki < 2; ++ki) {
            const int kb = ki * 16;
            uint32_t ah[4][4], bh[2][2];
#pragma unroll
            for (int mi = 0; mi < 4; mi++) {
                uint32_t adr = smb + (uint32_t)(cur * 10240
                             + (mi * 16 + lr + (qm & 1) * 8) * 80
                             + (kb + (qm >> 1) * 8) * 2);
                asm volatile("ldmatrix.sync.aligned.m8n8.x4.shared.b16 {%0,%1,%2,%3}, [%4];"
                             : "=r"(ah[mi][0]), "=r"(ah[mi][1]), "=r"(ah[mi][2]), "=r"(ah[mi][3])
                             : "r"(adr));
            }
            {
                uint32_t adr = smb + (uint32_t)(cur * 10240 + 5120
                             + (wid * 16 + lr + (qm >> 1) * 8) * 80
                             + (kb + (qm & 1) * 8) * 2);
                uint32_t t0, t1, t2, t3;
                asm volatile("ldmatrix.sync.aligned.m8n8.x4.shared.b16 {%0,%1,%2,%3}, [%4];"
                             : "=r"(t0), "=r"(t1), "=r"(t2), "=r"(t3) : "r"(adr));
                bh[0][0] = t0; bh[0][1] = t1; bh[1][0] = t2; bh[1][1] = t3;
            }
#pragma unroll
            for (int mi = 0; mi < 4; mi++)
#pragma unroll
                for (int ni = 0; ni < 2; ni++)
                    mma16816h(acc[mi][ni], ah[mi], bh[ni]);
        }
        __syncthreads();
        cur ^= 1;
    }
#undef GH_LOAD

#pragma unroll
    for (int mi = 0; mi < 4; mi++)
#pragma unroll
        for (int half = 0; half < 2; ++half) {
            int r = mi * 16 + g + half * 8;
#pragma unroll
            for (int ni = 0; ni < 2; ni++) {
                int col = ocol0 + wid * 16 + ni * 8 + 2 * tg;
                float2 v;
                v.x = acc[mi][ni][half * 2 + 0];
                v.y = acc[mi][ni][half * 2 + 1];
                if (bias1) { v.x += bias1[col]; v.y += bias1[col + 1]; }
                if (bias2) { v.x += bias2[col]; v.y += bias2[col + 1]; }
                if (HOUT) {
                    *(__half2*)((__half*)outp + (size_t)r * ostride + col) =
                        __floats2half2_rn(v.x, v.y);
                } else {
                    *(float2*)((float*)outp + (size_t)r * ostride + col) = v;
                }
            }
        }
}

// ===== hq: q-partials = h @ Wa^T (Bh rows 4096+) =========================
__global__ void __launch_bounds__(128)
hq_k()
{
    __shared__ __half sm[2 * 2 * 64 * 40];
    const int x = blockIdx.x;          // 0..15
    const int y = blockIdx.y;          // 0..3 k-slice
    gemm64x64h<false>(g_hH, g_BhH + (size_t)(4096 + x * 64) * Hd,
                      y * 256, 256, g_hp[y], 4096 + x * 64, NB5, nullptr, nullptr, sm);
}

// ===== hcgemm: h@W_hh^T (nt<64) and ctx@W_c^T (nt>=64) ===================
__global__ void __launch_bounds__(128)
hcgemm_k()
{
    __shared__ __half sm[2 * 2 * 64 * 40];
    const int nt = blockIdx.x;         // 0..127
    const int y = blockIdx.y;          // k-slice
    if (nt < 64) {
        gemm64x64h<false>(g_hH, g_BhH + (size_t)(nt * 64) * Hd,
                          y * 256, 256, g_hp[y], nt * 64, NB5, nullptr, nullptr, sm);
    } else {
        const int n = nt - 64;
        gemm64x64h<false>(g_ctxH, g_WcH + (size_t)(n * 64) * Hd,
                          y * 256, 256, g_cp[y], n * 64, 4096, nullptr, nullptr, sm);
    }
}

// ===== merged prologue GEMMs: xpre (z<14) and keys->fp16 (z>=14) =========
__global__ void __launch_bounds__(128)
pregemm(const float* __restrict__ b_ih, const float* __restrict__ b_hh,
        const float* __restrict__ bu)
{
    __shared__ __half sm[2 * 2 * 64 * 40];
    const int z = blockIdx.z;
    if (z < 14) {
        gemm64x64h<false>(g_xgH + (size_t)(z * 64) * Hd, g_WxH + (size_t)(blockIdx.x * 64) * Hd,
                          0, Hd, g_xpre + (size_t)(z * 64) * 4096, blockIdx.x * 64, 4096,
                          b_ih, b_hh, sm);
    } else {
        if (blockIdx.x >= 16) return;
        gemm64x64h<true>(g_encH + (size_t)((z - 14) * 64) * Hd, g_UaH + (size_t)(blockIdx.x * 64) * Hd,
                         0, Hd, g_keysH + (size_t)((z - 14) * 64) * Hd, blockIdx.x * 64, Hd,
                         bu, nullptr, sm);
    }
}

// ===== fused attend: scores (fp16 keys, 16B loads) + softmax + ctx (fp16) =
__global__ void __launch_bounds__(512)
attend_k(const float* __restrict__ Va, const float* __restrict__ ba,
         const float* __restrict__ bv, float* __restrict__ out_attn, int t)
{
    __shared__ float qs[Hd], vas[Hd];
    __shared__ float w[Ss];
    const int b = blockIdx.x;
    const int tid = threadIdx.x, wid = tid >> 5, lane = tid & 31;

    for (int k = tid; k < Hd; k += 512) {
        qs[k] = g_hp[0][b * NB5 + 4096 + k] + g_hp[1][b * NB5 + 4096 + k]
              + g_hp[2][b * NB5 + 4096 + k] + g_hp[3][b * NB5 + 4096 + k] + ba[k];
        vas[k] = Va[k];
    }
    __syncthreads();

    // 16 warps x 4 scores; 8 fp16 keys per 16B load; mufu/poly rule
    // identical to baseline: mufu iff ((k >> 5) & 15) < 7.
#pragma unroll
    for (int r = 0; r < 4; r++) {
        const int s = wid * 4 + r;
        const __half* kr = g_keysH + ((size_t)(b * Ss + s)) * Hd;
        float acc = 0.f;
#pragma unroll
        for (int i = 0; i < 4; i++) {
            int k = i * 256 + lane * 8;
            uint4 raw = *(const uint4*)(kr + k);
            float2 f01 = __half22float2(*reinterpret_cast<__half2*>(&raw.x));
            float2 f23 = __half22float2(*reinterpret_cast<__half2*>(&raw.y));
            float2 f45 = __half22float2(*reinterpret_cast<__half2*>(&raw.z));
            float2 f67 = __half22float2(*reinterpret_cast<__half2*>(&raw.w));
            float ke[8] = {f01.x, f01.y, f23.x, f23.y, f45.x, f45.y, f67.x, f67.y};
#pragma unroll
            for (int e = 0; e < 8; e++) {
                int kk = k + e;
                float v = qs[kk] + ke[e];
                float th = (((kk >> 5) & 15) < 7) ? tanh_mufu(v) : tanh_poly(v);
                acc += th * vas[kk];
            }
        }
#pragma unroll
        for (int o = 16; o; o >>= 1) acc += __shfl_xor_sync(0xffffffffu, acc, o);
        if (lane == 0) w[s] = acc + bv[0];
    }
    __syncthreads();

    if (tid < 32) {  // softmax over 64 by warp 0
        float v0 = w[tid], v1 = w[tid + 32];
        float m = fmaxf(v0, v1);
#pragma unroll
        for (int o = 16; o; o >>= 1) m = fmaxf(m, __shfl_xor_sync(0xffffffffu, m, o));
        float e0 = __expf(v0 - m), e1 = __expf(v1 - m);
        float sum = e0 + e1;
#pragma unroll
        for (int o = 16; o; o >>= 1) sum += __shfl_xor_sync(0xffffffffu, sum, o);
        float inv = 1.f / sum;
        w[tid] = e0 * inv; w[tid + 32] = e1 * inv;
    }
    __syncthreads();

    if (tid < Ss) out_attn[((size_t)b * Tt + t) * Ss + tid] = w[tid];

    // ctx from fp16 enc: 2 cols per thread
    float a0 = 0.f, a1 = 0.f;
#pragma unroll 8
    for (int s = 0; s < Ss; s++) {
        __half2 e2 = ((const __half2*)g_encH)[(size_t)(b * Ss + s) * 512 + tid];
        float2 e = __half22float2(e2);
        a0 += w[s] * e.x; a1 += w[s] * e.y;
    }
    ((__half2*)g_ctxH)[b * 512 + tid] = __floats2half2_rn(a0, a1);
}

// ===== cell: float4 partial reads; LSTM; LayerNorm -> bf16 nh ============
__global__ void __launch_bounds__(256)
cell_k(const float* __restrict__ ln_g, const float* __restrict__ ln_b, int t)
{
    const int b = blockIdx.x, tid = threadIdx.x;
    const int wid = tid >> 5, lane = tid & 31;
    __shared__ float r1[8], r2[8];
    const size_t xr = (size_t)(t * Bb + b) * 4096;

    const float4* xp = (const float4*)(g_xpre + xr);
    float4 vi = xp[tid];
    float4 vf = xp[256 + tid];
    float4 vg = xp[512 + tid];
    float4 vo = xp[768 + tid];

#define ADD4(d, s) { d.x += s.x; d.y += s.y; d.z += s.z; d.w += s.w; }
#pragma unroll
    for (int s = 0; s < 4; s++) {
        const float4* hp = (const float4*)(g_hp[s] + (size_t)b * NB5);
        float4 a0 = hp[tid], a1 = hp[256 + tid], a2 = hp[512 + tid], a3 = hp[768 + tid];
        ADD4(vi, a0) ADD4(vf, a1) ADD4(vg, a2) ADD4(vo, a3)
    }
#pragma unroll
    for (int s = 0; s < 4; s++) {
        const float4* cp = (const float4*)(g_cp[s] + (size_t)b * 4096);
        float4 a0 = cp[tid], a1 = cp[256 + tid], a2 = cp[512 + tid], a3 = cp[768 + tid];
        ADD4(vi, a0) ADD4(vf, a1) ADD4(vg, a2) ADD4(vo, a3)
    }
#undef ADD4

    float4 cold = ((const float4*)g_c)[b * 256 + tid];
    float gi[4] = {vi.x, vi.y, vi.z, vi.w};
    float gf[4] = {vf.x, vf.y, vf.z, vf.w};
    float gg[4] = {vg.x, vg.y, vg.z, vg.w};
    float go[4] = {vo.x, vo.y, vo.z, vo.w};
    float co[4] = {cold.x, cold.y, cold.z, cold.w};

    float hv[4], cn[4];
    float s1 = 0.f, s2 = 0.f;
#pragma unroll
    for (int e = 0; e < 4; e++) {
        float cv = sigmoid_fast(gf[e]) * co[e] + sigmoid_fast(gi[e]) * tanh_mufu(gg[e]);
        cn[e] = cv;
        float hh = sigmoid_fast(go[e]) * tanh_mufu(cv);
        hv[e] = hh; s1 += hh; s2 += hh * hh;
    }
    ((float4*)g_c)[b * 256 + tid] = make_float4(cn[0], cn[1], cn[2], cn[3]);
    ((float4*)g_h)[b * 256 + tid] = make_float4(hv[0], hv[1], hv[2], hv[3]);
    ((__half2*)g_hH)[b * 512 + tid * 2]     = __floats2half2_rn(hv[0], hv[1]);
    ((__half2*)g_hH)[b * 512 + tid * 2 + 1] = __floats2half2_rn(hv[2], hv[3]);

#pragma unroll
    for (int o = 16; o; o >>= 1) {
        s1 += __shfl_xor_sync(0xffffffffu, s1, o);
        s2 += __shfl_xor_sync(0xffffffffu, s2, o);
    }
    if (lane == 0) { r1[wid] = s1; r2[wid] = s2; }
    __syncthreads();
    if (wid == 0) {
        float a = (lane < 8) ? r1[lane] : 0.f;
        float q = (lane < 8) ? r2[lane] : 0.f;
#pragma unroll
        for (int o = 4; o; o >>= 1) {
            a += __shfl_xor_sync(0xffffffffu, a, o);
            q += __shfl_xor_sync(0xffffffffu, q, o);
        }
        if (lane == 0) { r1[0] = a; r2[0] = q; }
    }
    __syncthreads();
    float mu  = r1[0] * (1.f / Hd);
    float var = r2[0] * (1.f / Hd) - mu * mu;
    float inv = rsqrtf(var + 1e-5f);

    float4 lg = ((const float4*)ln_g)[tid];
    float4 lb = ((const float4*)ln_b)[tid];
    float lgv[4] = {lg.x, lg.y, lg.z, lg.w};
    float lbv[4] = {lb.x, lb.y, lb.z, lb.w};
    const size_t nb = (size_t)(t * Bb + b) * 512 + tid * 2;
    float n0 = (hv[0] - mu) * inv * lgv[0] + lbv[0];
    float n1 = (hv[1] - mu) * inv * lgv[1] + lbv[1];
    float n2 = (hv[2] - mu) * inv * lgv[2] + lbv[2];
    float n3 = (hv[3] - mu) * inv * lgv[3] + lbv[3];
    ((__nv_bfloat162*)g_nhb)[nb]     = __floats2bfloat162_rn(n0, n1);
    ((__nv_bfloat162*)g_nhb)[nb + 1] = __floats2bfloat162_rn(n2, n3);
}

// ===== one-time prep: ALL conversions + gather + state init, fused =======
__global__ void __launch_bounds__(256)
prep_all(const float* __restrict__ Whh, const float* __restrict__ Wa,
         const float* __restrict__ Wih, const float* __restrict__ Ua,
         const float* __restrict__ enc, const float* __restrict__ outW,
         const float* __restrict__ emb, const int* __restrict__ target,
         const float* __restrict__ h0, const float* __restrict__ c0)
{
    const int TOT = 51520 * 256;
    for (int idx = blockIdx.x * 256 + threadIdx.x; idx < TOT;
         idx += gridDim.x * 256) {
        int row = idx >> 8, c4 = idx & 255;

        if (row >= 18432 && row < 50432) {           // outW -> bf16 (most common)
            int r = row - 18432;
            float4 v = ((const float4*)(outW + ((size_t)r << 10)))[c4];
            size_t d4 = (size_t)r * 256 + c4;
            __nv_bfloat162* H = (__nv_bfloat162*)g_outWb;
            H[d4 * 2]     = __floats2bfloat162_rn(v.x, v.y);
            H[d4 * 2 + 1] = __floats2bfloat162_rn(v.z, v.w);
            continue;
        }
        if (row < 18432) {                           // fp16 conversions
            const float* src; __half* dst; size_t d4;
            if (row < 4096)       { src = Whh + ((size_t)row << 10);              dst = g_BhH; d4 = (size_t)row * 256 + c4; }
            else if (row < 5120)  { int r = row - 4096; src = Wa + ((size_t)r << 10);   dst = g_BhH; d4 = (size_t)row * 256 + c4; }
            else if (row < 9216)  { int r = row - 5120; src = Wih + ((size_t)r << 11);  dst = g_WxH; d4 = (size_t)r * 256 + c4; }
            else if (row < 13312) { int r = row - 9216; src = Wih + ((size_t)r << 11) + 1024; dst = g_WcH; d4 = (size_t)r * 256 + c4; }
            else if (row < 14336) { int r = row - 13312; src = Ua + ((size_t)r << 10);  dst = g_UaH; d4 = (size_t)r * 256 + c4; }
            else                  { int r = row - 14336; src = enc + ((size_t)r << 10); dst = g_encH; d4 = (size_t)r * 256 + c4; }
            float4 v = ((const float4*)src)[c4];
            __half2* H = (__half2*)dst;
            H[d4 * 2]     = __floats2half2_rn(v.x, v.y);
            H[d4 * 2 + 1] = __floats2half2_rn(v.z, v.w);
            continue;
        }
        if (row < 51328) {                           // embedding gather -> fp16
            int r = row - 50432;
            float4 v = make_float4(0.f, 0.f, 0.f, 0.f);
            if (r < Tt * Bb) {
                int t = r >> 6, b = r & 63;
                int tok = (t == 0) ? SOS_TOK : target[b * Tt + (t - 1)];
                v = ((const float4*)(emb + ((size_t)tok << 10)))[c4];
            }
            size_t d4 = (size_t)r * 256 + c4;
            __half2* H = (__half2*)g_xgH;
            H[d4 * 2]     = __floats2half2_rn(v.x, v.y);
            H[d4 * 2 + 1] = __floats2half2_rn(v.z, v.w);
            continue;
        }
        if (row < 51392) {                           // h0 init
            int r = row - 51328;
            size_t i4 = (size_t)r * 256 + c4;
            float4 v = ((const float4*)h0)[i4];
            ((float4*)g_h)[i4] = v;
            ((__half2*)g_hH)[i4 * 2]     = __floats2half2_rn(v.x, v.y);
            ((__half2*)g_hH)[i4 * 2 + 1] = __floats2half2_rn(v.z, v.w);
            continue;
        }
        if (row < 51456) {                           // c0 init
            int r = row - 51392;
            size_t i4 = (size_t)r * 256 + c4;
            ((float4*)g_c)[i4] = ((const float4*)c0)[i4];
            continue;
        }
        {                                            // nhb pad rows 832..895
            int r = row - 51456;
            __nv_bfloat162 z2 = __floats2bfloat162_rn(0.f, 0.f);
            size_t p = (((size_t)(832 + r) << 10) + c4 * 4) >> 1;
            ((__nv_bfloat162*)g_nhb)[p] = z2;
            ((__nv_bfloat162*)g_nhb)[p + 1] = z2;
        }
    }
}

// ================= big logits GEMM (bf16, unchanged R8) ===================
__global__ void __launch_bounds__(256)
logits_gemm(const __nv_bfloat16* __restrict__ A, const __nv_bfloat16* __restrict__ Bw,
            const float* __restrict__ bias, float* __restrict__ out)
{
    __shared__ __nv_bfloat16 As[2][128][40];
    __shared__ __nv_bfloat16 Bs[2][128][40];

    const int tid = threadIdx.x;
    const int wid = tid >> 5, lane = tid & 31;
    const int wm = wid & 1, wn = wid >> 1;
    const int g  = lane >> 2, tg = lane & 3;
    const int m0 = blockIdx.y * 128, n0 = blockIdx.x * 128;

    const uint32_t sA = (uint32_t)__cvta_generic_to_shared(&As[0][0][0]);
    const uint32_t sB = (uint32_t)__cvta_generic_to_shared(&Bs[0][0][0]);

    float acc[4][4][4];
#pragma unroll
    for (int a = 0; a < 4; a++)
#pragma unroll
        for (int b = 0; b < 4; b++)
#pragma unroll
            for (int c = 0; c < 4; c++) acc[a][b][c] = 0.f;

    const int idx0 = tid, idx1 = tid + 256;
    const int r0 = idx0 >> 2, c0 = (idx0 & 3) * 8;
    const int r1 = idx1 >> 2, c1 = (idx1 & 3) * 8;

#define LOAD_STAGE(st, k0)                                                          \
    {                                                                               \
        uint32_t da0 = sA + (uint32_t)((st) * 10240 + r0 * 80 + c0 * 2);            \
        uint32_t da1 = sA + (uint32_t)((st) * 10240 + r1 * 80 + c1 * 2);            \
        uint32_t db0 = sB + (uint32_t)((st) * 10240 + r0 * 80 + c0 * 2);            \
        uint32_t db1 = sB + (uint32_t)((st) * 10240 + r1 * 80 + c1 * 2);            \
        const __nv_bfloat16* sa0 = A + (size_t)(m0 + r0) * Hd + (k0) + c0;          \
        const __nv_bfloat16* sa1 = A + (size_t)(m0 + r1) * Hd + (k0) + c1;          \
        const __nv_bfloat16* sb0 = Bw + (size_t)(n0 + r0) * Hd + (k0) + c0;         \
        const __nv_bfloat16* sb1 = Bw + (size_t)(n0 + r1) * Hd + (k0) + c1;         \
        asm volatile("cp.async.cg.shared.global [%0], [%1], 16;\n" ::"r"(da0), "l"(sa0)); \
        asm volatile("cp.async.cg.shared.global [%0], [%1], 16;\n" ::"r"(da1), "l"(sa1)); \
        asm volatile("cp.async.cg.shared.global [%0], [%1], 16;\n" ::"r"(db0), "l"(sb0)); \
        asm volatile("cp.async.cg.shared.global [%0], [%1], 16;\n" ::"r"(db1), "l"(sb1)); \
    }

    LOAD_STAGE(0, 0)
    asm volatile("cp.async.commit_group;\n" ::: "memory");

    const int qm = lane >> 3, lr = lane & 7;

    int cur = 0;
#pragma unroll 1
    for (int k0 = 0; k0 < Hd; k0 += 32) {
        asm volatile("cp.async.wait_group 0;\n" ::: "memory");
        __syncthreads();
        if (k0 + 32 < Hd) {
            LOAD_STAGE(cur ^ 1, k0 + 32)
            asm volatile("cp.async.commit_group;\n" ::: "memory");
        }

#pragma unroll
        for (int ki = 0; ki < 2; ++ki) {
            const int kb = ki * 16;
            uint32_t af[4][4], bf[4][2];
#pragma unroll
            for (int mi = 0; mi < 4; mi++) {
                int rr = wm * 64 + mi * 16;
                uint32_t addr = sA + (uint32_t)(cur * 10240
                              + (rr + lr + (qm & 1) * 8) * 80
                              + (kb + (qm >> 1) * 8) * 2);
                asm volatile("ldmatrix.sync.aligned.m8n8.x4.shared.b16 {%0,%1,%2,%3}, [%4];"
                             : "=r"(af[mi][0]), "=r"(af[mi][1]), "=r"(af[mi][2]), "=r"(af[mi][3])
                             : "r"(addr));
            }
#pragma unroll
            for (int np = 0; np < 2; np++) {
                int nr = wn * 32 + np * 16;
                uint32_t addr = sB + (uint32_t)(cur * 10240
                              + (nr + lr + (qm >> 1) * 8) * 80
                              + (kb + (qm & 1) * 8) * 2);
                uint32_t t0, t1, t2, t3;
                asm volatile("ldmatrix.sync.aligned.m8n8.x4.shared.b16 {%0,%1,%2,%3}, [%4];"
                             : "=r"(t0), "=r"(t1), "=r"(t2), "=r"(t3)
                             : "r"(addr));
                bf[np * 2][0] = t0; bf[np * 2][1] = t1;
                bf[np * 2 + 1][0] = t2; bf[np * 2 + 1][1] = t3;
            }
#pragma unroll
            for (int mi = 0; mi < 4; mi++)
#pragma unroll
                for (int ni = 0; ni < 4; ni++)
                    mma16816bf(acc[mi][ni], af[mi], bf[ni]);
        }
        __syncthreads();
        cur ^= 1;
    }

#pragma unroll
    for (int mi = 0; mi < 4; mi++)
#pragma unroll
        for (int half = 0; half < 2; ++half) {
            int row = m0 + wm * 64 + mi * 16 + g + half * 8;
            if (row < Tt * Bb) {
                size_t orow = (size_t)(row & 63) * Tt + (row >> 6);
#pragma unroll
                for (int ni = 0; ni < 4; ni++) {
                    int col = n0 + wn * 32 + ni * 8 + 2 * tg;
                    float2 v;
                    v.x = acc[mi][ni][half * 2 + 0] + bias[col];
                    v.y = acc[mi][ni][half * 2 + 1] + bias[col + 1];
                    *(float2*)(out + orow * (size_t)Vv + col) = v;
                }
            }
        }
#undef LOAD_STAGE
}

// ---------------- log-softmax (blocks < 832) + h/c copy (blocks >= 832) ---
__global__ void __launch_bounds__(512)
lsm_copy(float* __restrict__ out)
{
    if (blockIdx.x >= Tt * Bb) {
        int base = (blockIdx.x - Tt * Bb) * 512 + threadIdx.x;
        for (int i = base; i < Bb * Hd; i += 16 * 512) {
            out[(size_t)Bb * Tt * Vv + i] = g_h[i];
            out[(size_t)Bb * Tt * Vv + (size_t)Bb * Hd + i] = g_c[i];
        }
        return;
    }
    const size_t bse = (size_t)blockIdx.x * Vv;
    const int tid = threadIdx.x;
    const int wid = tid >> 5, lane = tid & 31;
    __shared__ float rm[16], rs[16], fin[2];

    float m = -1e30f, s = 0.f;
    const float4* p = (const float4*)(out + bse);
    for (int i = tid; i < Vv / 4; i += 512) {
        float4 v = p[i];
        float xs[4] = {v.x, v.y, v.z, v.w};
#pragma unroll
        for (int e = 0; e < 4; e++) {
            float nm = fmaxf(m, xs[e]);
            s = s * __expf(m - nm) + __expf(xs[e] - nm);
            m = nm;
        }
    }
#pragma unroll
    for (int o = 16; o; o >>= 1) {
        float om = __shfl_xor_sync(0xffffffffu, m, o);
        float os = __shfl_xor_sync(0xffffffffu, s, o);
        float nm = fmaxf(m, om);
        s = s * __expf(m - nm) + os * __expf(om - nm);
        m = nm;
    }
    if (lane == 0) { rm[wid] = m; rs[wid] = s; }
    __syncthreads();
    if (wid == 0) {
        float mm = (lane < 16) ? rm[lane] : -1e30f;
        float ss = (lane < 16) ? rs[lane] : 0.f;
#pragma unroll
        for (int o = 8; o; o >>= 1) {
            float om = __shfl_xor_sync(0xffffffffu, mm, o);
            float os = __shfl_xor_sync(0xffffffffu, ss, o);
            float nm = fmaxf(mm, om);
            ss = ss * __expf(mm - nm) + os * __expf(om - nm);
            mm = nm;
        }
        if (lane == 0) { fin[0] = mm; fin[1] = ss; }
    }
    __syncthreads();
    float lse = fin[0] + logf(fin[1]);
    float4* q = (float4*)(out + bse);
    for (int i = tid; i < Vv / 4; i += 512) {
        float4 v = q[i];
        v.x -= lse; v.y -= lse; v.z -= lse; v.w -= lse;
        q[i] = v;
    }
}

// ---------------- launch ---------------------------------------------------
extern "C" void kernel_launch(void* const* d_in, const int* in_sizes, int n_in,
                              void* d_out, int out_size)
{
    (void)in_sizes; (void)n_in; (void)out_size;
    const float* enc    = (const float*)d_in[0];
    const float* enc_h  = (const float*)d_in[1];
    const float* enc_c  = (const float*)d_in[2];
    const int*   target = (const int*)  d_in[3];
    const float* emb    = (const float*)d_in[4];
    const float* Wa     = (const float*)d_in[5];
    const float* ba     = (const float*)d_in[6];
    const float* Ua     = (const float*)d_in[7];
    const float* bu     = (const float*)d_in[8];
    const float* Va     = (const float*)d_in[9];
    const float* bv     = (const float*)d_in[10];
    const float* W_ih   = (const float*)d_in[11];
    const float* W_hh   = (const float*)d_in[12];
    const float* b_ih   = (const float*)d_in[13];
    const float* b_hh   = (const float*)d_in[14];
    const float* ln_g   = (const float*)d_in[15];
    const float* ln_b   = (const float*)d_in[16];
    const float* outW   = (const float*)d_in[17];
    const float* outb   = (const float*)d_in[18];
    float* out = (float*)d_out;

    __nv_bfloat16 *nhb, *outWb;
    cudaGetSymbolAddress((void**)&nhb,   g_nhb);
    cudaGetSymbolAddress((void**)&outWb, g_outWb);

    float* out_attn = out + (size_t)Bb * Tt * Vv + 2 * (size_t)Bb * Hd;

    // (0) all conversions + embedding gather + state init, one launch
    prep_all<<<2048, 256>>>(W_hh, Wa, W_ih, Ua, enc, outW, emb, target,
                            enc_h, enc_c);
    // (1) xpre + keys(fp16), one launch
    pregemm<<<dim3(64, 1, 78), 128>>>(b_ih, b_hh, bu);

    for (int t = 0; t < Tt; t++) {
        hq_k<<<dim3(16, 4), 128>>>();                                 // q partials
        attend_k<<<Bb, 512>>>(Va, ba, bv, out_attn, t);               // scores+softmax+ctx
        hcgemm_k<<<dim3(128, 4), 128>>>();                            // h@Whh + ctx@Wc
        cell_k<<<Bb, 256>>>(ln_g, ln_b, t);                           // LSTM + LN
    }

    logits_gemm<<<dim3(Vv / 128, 7), 256>>>(nhb, outWb, outb, out);
    lsm_copy<<<Tt * Bb + 16, 512>>>(out);
}

// round 17
// speedup vs baseline: 1.0426x; 1.0426x over previous
#include <cuda_runtime.h>
#include <cuda_bf16.h>
#include <cuda_fp16.h>
#include <cstdint>

#define Hd 1024
#define Vv 32000
#define Bb 64
#define Ss 64
#define Tt 13
#define SOS_TOK 2
#define NB5 5120   // W_hh rows (4096) + Wa rows (1024)

// ---------------- static scratch ------------------------------------------
__device__ float g_h[Bb * Hd];
__device__ float g_c[Bb * Hd];
__device__ float g_sc[Bb * Ss];
__device__ float g_hp[4][Bb * NB5];          // h@[W_hh|Wa]^T partials (4 k-slices)
__device__ float g_cp[4][Bb * 4096];         // ctx@W_ihc^T partials
__device__ float g_xpre[896 * 4096];         // x@W_ihx^T + b_ih + b_hh (all steps)

__device__ __half g_keysH[Bb * Ss * Hd];     // keys_proj (fp16)
__device__ __half g_hH[Bb * Hd];             // h (fp16)
__device__ __half g_ctxH[Bb * Hd];           // ctx (fp16)
__device__ __half g_encH[Bb * Ss * Hd];      // enc (fp16)
__device__ __half g_UaH[Hd * Hd];
__device__ __half g_BhH[NB5 * Hd];           // [W_hh;Wa]
__device__ __half g_WxH[4096 * Hd];          // W_ih x-cols
__device__ __half g_WcH[4096 * Hd];          // W_ih ctx-cols
__device__ __half g_xgH[896 * Hd];           // gathered emb
__device__ __nv_bfloat16 g_nhb[896 * Hd];
__device__ __nv_bfloat16 g_outWb[(size_t)Vv * Hd];

// ---------------- math helpers -------------------------------------------
__device__ __forceinline__ float rcp_fast(float d) {
    float r = __int_as_float(0x7EF311C3 - __float_as_int(d));
    r = r * __fmaf_rn(-d, r, 2.0f);
    r = r * __fmaf_rn(-d, r, 2.0f);
    return r;
}
__device__ __forceinline__ float tanh_mufu(float x) {
    float y;
    asm("tanh.approx.f32 %0, %1;" : "=f"(y) : "f"(x));
    return y;
}
__device__ __forceinline__ float tanh_poly(float x) {
    float cx = fminf(fmaxf(x, -4.97f), 4.97f);
    float t = cx * cx;
    float p = t + 378.f;
    p = __fmaf_rn(p, t, 17325.f);
    p = __fmaf_rn(p, t, 135135.f);
    p = p * cx;
    float q = __fmaf_rn(28.f, t, 3150.f);
    q = __fmaf_rn(q, t, 62370.f);
    q = __fmaf_rn(q, t, 135135.f);
    return p * rcp_fast(q);
}
__device__ __forceinline__ float sigmoid_fast(float x) {
    return rcp_fast(1.f + __expf(-x));
}

// ---------------- mma helpers --------------------------------------------
__device__ __forceinline__ void mma16816bf(float* d, const uint32_t* a, const uint32_t* b) {
    asm volatile(
        "mma.sync.aligned.m16n8k16.row.col.f32.bf16.bf16.f32 "
        "{%0,%1,%2,%3}, {%4,%5,%6,%7}, {%8,%9}, {%0,%1,%2,%3};\n"
        : "+f"(d[0]), "+f"(d[1]), "+f"(d[2]), "+f"(d[3])
        : "r"(a[0]), "r"(a[1]), "r"(a[2]), "r"(a[3]), "r"(b[0]), "r"(b[1]));
}
__device__ __forceinline__ void mma16816h(float* d, const uint32_t* a, const uint32_t* b) {
    asm volatile(
        "mma.sync.aligned.m16n8k16.row.col.f32.f16.f16.f32 "
        "{%0,%1,%2,%3}, {%4,%5,%6,%7}, {%8,%9}, {%0,%1,%2,%3};\n"
        : "+f"(d[0]), "+f"(d[1]), "+f"(d[2]), "+f"(d[3])
        : "r"(a[0]), "r"(a[1]), "r"(a[2]), "r"(a[3]), "r"(b[0]), "r"(b[1]));
}

// ===== 64m x 64n fp16 GEMM body, 128 thr, variable K window ==============
template<bool HOUT>
__device__ __forceinline__ void gemm64x64h(
    const __half* __restrict__ Ah, const __half* __restrict__ Bh,
    int kb0, int kw, void* __restrict__ outp, int ocol0, int ostride,
    const float* __restrict__ bias1, const float* __restrict__ bias2,
    __half* smp)
{
    const int K = Hd;
    const int tid = threadIdx.x;
    const int wid = tid >> 5, lane = tid & 31;
    const int g = lane >> 2, tg = lane & 3;
    const int qm = lane >> 3, lr = lane & 7;
    const uint32_t smb = (uint32_t)__cvta_generic_to_shared(smp);

    float acc[4][2][4];
#pragma unroll
    for (int a = 0; a < 4; a++)
#pragma unroll
        for (int b = 0; b < 2; b++)
#pragma unroll
            for (int c = 0; c < 4; c++) acc[a][b][c] = 0.f;

#define GH_LOAD(st, k0)                                                             \
    {                                                                               \
        _Pragma("unroll")                                                           \
        for (int rep = 0; rep < 2; ++rep) {                                         \
            int idx = tid + rep * 128;                                              \
            int row = idx >> 2, c8 = (idx & 3) * 8;                                 \
            uint32_t d0 = smb + (uint32_t)((st) * 10240 + row * 80 + c8 * 2);       \
            asm volatile("cp.async.cg.shared.global [%0], [%1], 16;\n"              \
                         ::"r"(d0), "l"(Ah + (size_t)row * K + (k0) + c8));         \
            asm volatile("cp.async.cg.shared.global [%0], [%1], 16;\n"              \
                         ::"r"(d0 + 5120), "l"(Bh + (size_t)row * K + (k0) + c8));  \
        }                                                                           \
    }

    GH_LOAD(0, kb0)
    asm volatile("cp.async.commit_group;\n" ::: "memory");

    int cur = 0;
#pragma unroll 1
    for (int k0 = kb0; k0 < kb0 + kw; k0 += 32) {
        asm volatile("cp.async.wait_group 0;\n" ::: "memory");
        __syncthreads();
        if (k0 + 32 < kb0 + kw) {
            GH_LOAD(cur ^ 1, k0 + 32)
            asm volatile("cp.async.commit_group;\n" ::: "memory");
        }

#pragma unroll
        for (int ki = 0; ki < 2; ++ki) {
            const int kb = ki * 16;
            uint32_t ah[4][4], bh[2][2];
#pragma unroll
            for (int mi = 0; mi < 4; mi++) {
                uint32_t adr = smb + (uint32_t)(cur * 10240
                             + (mi * 16 + lr + (qm & 1) * 8) * 80
                             + (kb + (qm >> 1) * 8) * 2);
                asm volatile("ldmatrix.sync.aligned.m8n8.x4.shared.b16 {%0,%1,%2,%3}, [%4];"
                             : "=r"(ah[mi][0]), "=r"(ah[mi][1]), "=r"(ah[mi][2]), "=r"(ah[mi][3])
                             : "r"(adr));
            }
            {
                uint32_t adr = smb + (uint32_t)(cur * 10240 + 5120
                             + (wid * 16 + lr + (qm >> 1) * 8) * 80
                             + (kb + (qm & 1) * 8) * 2);
                uint32_t t0, t1, t2, t3;
                asm volatile("ldmatrix.sync.aligned.m8n8.x4.shared.b16 {%0,%1,%2,%3}, [%4];"
                             : "=r"(t0), "=r"(t1), "=r"(t2), "=r"(t3) : "r"(adr));
                bh[0][0] = t0; bh[0][1] = t1; bh[1][0] = t2; bh[1][1] = t3;
            }
#pragma unroll
            for (int mi = 0; mi < 4; mi++)
#pragma unroll
                for (int ni = 0; ni < 2; ni++)
                    mma16816h(acc[mi][ni], ah[mi], bh[ni]);
        }
        __syncthreads();
        cur ^= 1;
    }
#undef GH_LOAD

#pragma unroll
    for (int mi = 0; mi < 4; mi++)
#pragma unroll
        for (int half = 0; half < 2; ++half) {
            int r = mi * 16 + g + half * 8;
#pragma unroll
            for (int ni = 0; ni < 2; ni++) {
                int col = ocol0 + wid * 16 + ni * 8 + 2 * tg;
                float2 v;
                v.x = acc[mi][ni][half * 2 + 0];
                v.y = acc[mi][ni][half * 2 + 1];
                if (bias1) { v.x += bias1[col]; v.y += bias1[col + 1]; }
                if (bias2) { v.x += bias2[col]; v.y += bias2[col + 1]; }
                if (HOUT) {
                    *(__half2*)((__half*)outp + (size_t)r * ostride + col) =
                        __floats2half2_rn(v.x, v.y);
                } else {
                    *(float2*)((float*)outp + (size_t)r * ostride + col) = v;
                }
            }
        }
}

// ===== hq: q-partials = h @ Wa^T (Bh rows 4096+) =========================
__global__ void __launch_bounds__(128)
hq_k()
{
    __shared__ __half sm[2 * 2 * 64 * 40];
    const int x = blockIdx.x;          // 0..15
    const int y = blockIdx.y;          // 0..3 k-slice
    gemm64x64h<false>(g_hH, g_BhH + (size_t)(4096 + x * 64) * Hd,
                      y * 256, 256, g_hp[y], 4096 + x * 64, NB5, nullptr, nullptr, sm);
}

// ===== hcgemm: h@W_hh^T (nt<64) and ctx@W_c^T (nt>=64) ===================
__global__ void __launch_bounds__(128)
hcgemm_k()
{
    __shared__ __half sm[2 * 2 * 64 * 40];
    const int nt = blockIdx.x;         // 0..127
    const int y = blockIdx.y;          // k-slice
    if (nt < 64) {
        gemm64x64h<false>(g_hH, g_BhH + (size_t)(nt * 64) * Hd,
                          y * 256, 256, g_hp[y], nt * 64, NB5, nullptr, nullptr, sm);
    } else {
        const int n = nt - 64;
        gemm64x64h<false>(g_ctxH, g_WcH + (size_t)(n * 64) * Hd,
                          y * 256, 256, g_cp[y], n * 64, 4096, nullptr, nullptr, sm);
    }
}

// ===== merged prologue GEMMs: xpre (z<14) and keys->fp16 (z>=14) =========
__global__ void __launch_bounds__(128)
pregemm(const float* __restrict__ b_ih, const float* __restrict__ b_hh,
        const float* __restrict__ bu)
{
    __shared__ __half sm[2 * 2 * 64 * 40];
    const int z = blockIdx.z;
    if (z < 14) {
        gemm64x64h<false>(g_xgH + (size_t)(z * 64) * Hd, g_WxH + (size_t)(blockIdx.x * 64) * Hd,
                          0, Hd, g_xpre + (size_t)(z * 64) * 4096, blockIdx.x * 64, 4096,
                          b_ih, b_hh, sm);
    } else {
        if (blockIdx.x >= 16) return;
        gemm64x64h<true>(g_encH + (size_t)((z - 14) * 64) * Hd, g_UaH + (size_t)(blockIdx.x * 64) * Hd,
                         0, Hd, g_keysH + (size_t)((z - 14) * 64) * Hd, blockIdx.x * 64, Hd,
                         bu, nullptr, sm);
    }
}

// ===== scores: grid (64, 8), 256 thr; 1 warp per score; fp16 keys ========
__global__ void __launch_bounds__(256)
scores_k(const float* __restrict__ Va, const float* __restrict__ ba,
         const float* __restrict__ bv)
{
    __shared__ float qs[Hd], vas[Hd];
    const int b = blockIdx.x;
    const int tid = threadIdx.x, wid = tid >> 5, lane = tid & 31;

    for (int k = tid; k < Hd; k += 256) {
        qs[k] = g_hp[0][b * NB5 + 4096 + k] + g_hp[1][b * NB5 + 4096 + k]
              + g_hp[2][b * NB5 + 4096 + k] + g_hp[3][b * NB5 + 4096 + k] + ba[k];
        vas[k] = Va[k];
    }
    __syncthreads();

    const int s = blockIdx.y * 8 + wid;
    const __half* kr = g_keysH + ((size_t)(b * Ss + s)) * Hd;
    float acc = 0.f;
    // 4 x 16B loads per lane; mufu/poly rule identical: mufu iff ((k>>5)&15)<7
#pragma unroll
    for (int i = 0; i < 4; i++) {
        int k = i * 256 + lane * 8;
        uint4 raw = *(const uint4*)(kr + k);
        float2 f01 = __half22float2(*reinterpret_cast<__half2*>(&raw.x));
        float2 f23 = __half22float2(*reinterpret_cast<__half2*>(&raw.y));
        float2 f45 = __half22float2(*reinterpret_cast<__half2*>(&raw.z));
        float2 f67 = __half22float2(*reinterpret_cast<__half2*>(&raw.w));
        float ke[8] = {f01.x, f01.y, f23.x, f23.y, f45.x, f45.y, f67.x, f67.y};
#pragma unroll
        for (int e = 0; e < 8; e++) {
            int kk = k + e;
            float v = qs[kk] + ke[e];
            float th = (((kk >> 5) & 15) < 7) ? tanh_mufu(v) : tanh_poly(v);
            acc += th * vas[kk];
        }
    }
#pragma unroll
    for (int o = 16; o; o >>= 1) acc += __shfl_xor_sync(0xffffffffu, acc, o);
    if (lane == 0) g_sc[b * Ss + s] = acc + bv[0];
}

// ===== ctx: grid (64, 4), 128 thr; softmax recompute; half2 enc ==========
__global__ void __launch_bounds__(128)
ctx_k(float* __restrict__ out_attn, int t)
{
    __shared__ float w[Ss];
    const int b = blockIdx.x, hq = blockIdx.y;
    const int tid = threadIdx.x;

    if (tid < Ss) w[tid] = g_sc[b * Ss + tid];
    __syncthreads();
    if (tid < 32) {
        float v0 = w[tid], v1 = w[tid + 32];
        float m = fmaxf(v0, v1);
#pragma unroll
        for (int o = 16; o; o >>= 1) m = fmaxf(m, __shfl_xor_sync(0xffffffffu, m, o));
        float e0 = __expf(v0 - m), e1 = __expf(v1 - m);
        float sum = e0 + e1;
#pragma unroll
        for (int o = 16; o; o >>= 1) sum += __shfl_xor_sync(0xffffffffu, sum, o);
        float inv = 1.f / sum;
        w[tid] = e0 * inv; w[tid + 32] = e1 * inv;
    }
    __syncthreads();

    if (hq == 0 && tid < Ss) out_attn[((size_t)b * Tt + t) * Ss + tid] = w[tid];

    const int c2 = hq * 128 + tid;          // half2 column index (0..511)
    float a0 = 0.f, a1 = 0.f;
#pragma unroll 8
    for (int s = 0; s < Ss; s++) {
        __half2 e2 = ((const __half2*)g_encH)[(size_t)(b * Ss + s) * 512 + c2];
        float2 e = __half22float2(e2);
        a0 += w[s] * e.x; a1 += w[s] * e.y;
    }
    ((__half2*)g_ctxH)[b * 512 + c2] = __floats2half2_rn(a0, a1);
}

// ===== cell: float4 partial reads; LSTM; LayerNorm -> bf16 nh ============
__global__ void __launch_bounds__(256)
cell_k(const float* __restrict__ ln_g, const float* __restrict__ ln_b, int t)
{
    const int b = blockIdx.x, tid = threadIdx.x;
    const int wid = tid >> 5, lane = tid & 31;
    __shared__ float r1[8], r2[8];
    const size_t xr = (size_t)(t * Bb + b) * 4096;

    const float4* xp = (const float4*)(g_xpre + xr);
    float4 vi = xp[tid];
    float4 vf = xp[256 + tid];
    float4 vg = xp[512 + tid];
    float4 vo = xp[768 + tid];

#define ADD4(d, s) { d.x += s.x; d.y += s.y; d.z += s.z; d.w += s.w; }
#pragma unroll
    for (int s = 0; s < 4; s++) {
        const float4* hp = (const float4*)(g_hp[s] + (size_t)b * NB5);
        float4 a0 = hp[tid], a1 = hp[256 + tid], a2 = hp[512 + tid], a3 = hp[768 + tid];
        ADD4(vi, a0) ADD4(vf, a1) ADD4(vg, a2) ADD4(vo, a3)
    }
#pragma unroll
    for (int s = 0; s < 4; s++) {
        const float4* cp = (const float4*)(g_cp[s] + (size_t)b * 4096);
        float4 a0 = cp[tid], a1 = cp[256 + tid], a2 = cp[512 + tid], a3 = cp[768 + tid];
        ADD4(vi, a0) ADD4(vf, a1) ADD4(vg, a2) ADD4(vo, a3)
    }
#undef ADD4

    float4 cold = ((const float4*)g_c)[b * 256 + tid];
    float gi[4] = {vi.x, vi.y, vi.z, vi.w};
    float gf[4] = {vf.x, vf.y, vf.z, vf.w};
    float gg[4] = {vg.x, vg.y, vg.z, vg.w};
    float go[4] = {vo.x, vo.y, vo.z, vo.w};
    float co[4] = {cold.x, cold.y, cold.z, cold.w};

    float hv[4], cn[4];
    float s1 = 0.f, s2 = 0.f;
#pragma unroll
    for (int e = 0; e < 4; e++) {
        float cv = sigmoid_fast(gf[e]) * co[e] + sigmoid_fast(gi[e]) * tanh_mufu(gg[e]);
        cn[e] = cv;
        float hh = sigmoid_fast(go[e]) * tanh_mufu(cv);
        hv[e] = hh; s1 += hh; s2 += hh * hh;
    }
    ((float4*)g_c)[b * 256 + tid] = make_float4(cn[0], cn[1], cn[2], cn[3]);
    ((float4*)g_h)[b * 256 + tid] = make_float4(hv[0], hv[1], hv[2], hv[3]);
    ((__half2*)g_hH)[b * 512 + tid * 2]     = __floats2half2_rn(hv[0], hv[1]);
    ((__half2*)g_hH)[b * 512 + tid * 2 + 1] = __floats2half2_rn(hv[2], hv[3]);

#pragma unroll
    for (int o = 16; o; o >>= 1) {
        s1 += __shfl_xor_sync(0xffffffffu, s1, o);
        s2 += __shfl_xor_sync(0xffffffffu, s2, o);
    }
    if (lane == 0) { r1[wid] = s1; r2[wid] = s2; }
    __syncthreads();
    if (wid == 0) {
        float a = (lane < 8) ? r1[lane] : 0.f;
        float q = (lane < 8) ? r2[lane] : 0.f;
#pragma unroll
        for (int o = 4; o; o >>= 1) {
            a += __shfl_xor_sync(0xffffffffu, a, o);
            q += __shfl_xor_sync(0xffffffffu, q, o);
        }
        if (lane == 0) { r1[0] = a; r2[0] = q; }
    }
    __syncthreads();
    float mu  = r1[0] * (1.f / Hd);
    float var = r2[0] * (1.f / Hd) - mu * mu;
    float inv = rsqrtf(var + 1e-5f);

    float4 lg = ((const float4*)ln_g)[tid];
    float4 lb = ((const float4*)ln_b)[tid];
    float lgv[4] = {lg.x, lg.y, lg.z, lg.w};
    float lbv[4] = {lb.x, lb.y, lb.z, lb.w};
    const size_t nb = (size_t)(t * Bb + b) * 512 + tid * 2;
    float n0 = (hv[0] - mu) * inv * lgv[0] + lbv[0];
    float n1 = (hv[1] - mu) * inv * lgv[1] + lbv[1];
    float n2 = (hv[2] - mu) * inv * lgv[2] + lbv[2];
    float n3 = (hv[3] - mu) * inv * lgv[3] + lbv[3];
    ((__nv_bfloat162*)g_nhb)[nb]     = __floats2bfloat162_rn(n0, n1);
    ((__nv_bfloat162*)g_nhb)[nb + 1] = __floats2bfloat162_rn(n2, n3);
}

// ===== one-time prep: ALL conversions + gather + state init, fused =======
__global__ void __launch_bounds__(256)
prep_all(const float* __restrict__ Whh, const float* __restrict__ Wa,
         const float* __restrict__ Wih, const float* __restrict__ Ua,
         const float* __restrict__ enc, const float* __restrict__ outW,
         const float* __restrict__ emb, const int* __restrict__ target,
         const float* __restrict__ h0, const float* __restrict__ c0)
{
    const int TOT = 51520 * 256;
    for (int idx = blockIdx.x * 256 + threadIdx.x; idx < TOT;
         idx += gridDim.x * 256) {
        int row = idx >> 8, c4 = idx & 255;

        if (row >= 18432 && row < 50432) {           // outW -> bf16 (most common)
            int r = row - 18432;
            float4 v = ((const float4*)(outW + ((size_t)r << 10)))[c4];
            size_t d4 = (size_t)r * 256 + c4;
            __nv_bfloat162* H = (__nv_bfloat162*)g_outWb;
            H[d4 * 2]     = __floats2bfloat162_rn(v.x, v.y);
            H[d4 * 2 + 1] = __floats2bfloat162_rn(v.z, v.w);
            continue;
        }
        if (row < 18432) {                           // fp16 conversions
            const float* src; __half* dst; size_t d4;
            if (row < 4096)       { src = Whh + ((size_t)row << 10);              dst = g_BhH; d4 = (size_t)row * 256 + c4; }
            else if (row < 5120)  { int r = row - 4096; src = Wa + ((size_t)r << 10);   dst = g_BhH; d4 = (size_t)row * 256 + c4; }
            else if (row < 9216)  { int r = row - 5120; src = Wih + ((size_t)r << 11);  dst = g_WxH; d4 = (size_t)r * 256 + c4; }
            else if (row < 13312) { int r = row - 9216; src = Wih + ((size_t)r << 11) + 1024; dst = g_WcH; d4 = (size_t)r * 256 + c4; }
            else if (row < 14336) { int r = row - 13312; src = Ua + ((size_t)r << 10);  dst = g_UaH; d4 = (size_t)r * 256 + c4; }
            else                  { int r = row - 14336; src = enc + ((size_t)r << 10); dst = g_encH; d4 = (size_t)r * 256 + c4; }
            float4 v = ((const float4*)src)[c4];
            __half2* H = (__half2*)dst;
            H[d4 * 2]     = __floats2half2_rn(v.x, v.y);
            H[d4 * 2 + 1] = __floats2half2_rn(v.z, v.w);
            continue;
        }
        if (row < 51328) {                           // embedding gather -> fp16
            int r = row - 50432;
            float4 v = make_float4(0.f, 0.f, 0.f, 0.f);
            if (r < Tt * Bb) {
                int t = r >> 6, b = r & 63;
                int tok = (t == 0) ? SOS_TOK : target[b * Tt + (t - 1)];
                v = ((const float4*)(emb + ((size_t)tok << 10)))[c4];
            }
            size_t d4 = (size_t)r * 256 + c4;
            __half2* H = (__half2*)g_xgH;
            H[d4 * 2]     = __floats2half2_rn(v.x, v.y);
            H[d4 * 2 + 1] = __floats2half2_rn(v.z, v.w);
            continue;
        }
        if (row < 51392) {                           // h0 init
            int r = row - 51328;
            size_t i4 = (size_t)r * 256 + c4;
            float4 v = ((const float4*)h0)[i4];
            ((float4*)g_h)[i4] = v;
            ((__half2*)g_hH)[i4 * 2]     = __floats2half2_rn(v.x, v.y);
            ((__half2*)g_hH)[i4 * 2 + 1] = __floats2half2_rn(v.z, v.w);
            continue;
        }
        if (row < 51456) {                           // c0 init
            int r = row - 51392;
            size_t i4 = (size_t)r * 256 + c4;
            ((float4*)g_c)[i4] = ((const float4*)c0)[i4];
            continue;
        }
        {                                            // nhb pad rows 832..895
            int r = row - 51456;
            __nv_bfloat162 z2 = __floats2bfloat162_rn(0.f, 0.f);
            size_t p = (((size_t)(832 + r) << 10) + c4 * 4) >> 1;
            ((__nv_bfloat162*)g_nhb)[p] = z2;
            ((__nv_bfloat162*)g_nhb)[p + 1] = z2;
        }
    }
}

// ================= big logits GEMM (bf16, unchanged R8) ===================
__global__ void __launch_bounds__(256)
logits_gemm(const __nv_bfloat16* __restrict__ A, const __nv_bfloat16* __restrict__ Bw,
            const float* __restrict__ bias, float* __restrict__ out)
{
    __shared__ __nv_bfloat16 As[2][128][40];
    __shared__ __nv_bfloat16 Bs[2][128][40];

    const int tid = threadIdx.x;
    const int wid = tid >> 5, lane = tid & 31;
    const int wm = wid & 1, wn = wid >> 1;
    const int g  = lane >> 2, tg = lane & 3;
    const int m0 = blockIdx.y * 128, n0 = blockIdx.x * 128;

    const uint32_t sA = (uint32_t)__cvta_generic_to_shared(&As[0][0][0]);
    const uint32_t sB = (uint32_t)__cvta_generic_to_shared(&Bs[0][0][0]);

    float acc[4][4][4];
#pragma unroll
    for (int a = 0; a < 4; a++)
#pragma unroll
        for (int b = 0; b < 4; b++)
#pragma unroll
            for (int c = 0; c < 4; c++) acc[a][b][c] = 0.f;

    const int idx0 = tid, idx1 = tid + 256;
    const int r0 = idx0 >> 2, c0 = (idx0 & 3) * 8;
    const int r1 = idx1 >> 2, c1 = (idx1 & 3) * 8;

#define LOAD_STAGE(st, k0)                                                          \
    {                                                                               \
        uint32_t da0 = sA + (uint32_t)((st) * 10240 + r0 * 80 + c0 * 2);            \
        uint32_t da1 = sA + (uint32_t)((st) * 10240 + r1 * 80 + c1 * 2);            \
        uint32_t db0 = sB + (uint32_t)((st) * 10240 + r0 * 80 + c0 * 2);            \
        uint32_t db1 = sB + (uint32_t)((st) * 10240 + r1 * 80 + c1 * 2);            \
        const __nv_bfloat16* sa0 = A + (size_t)(m0 + r0) * Hd + (k0) + c0;          \
        const __nv_bfloat16* sa1 = A + (size_t)(m0 + r1) * Hd + (k0) + c1;          \
        const __nv_bfloat16* sb0 = Bw + (size_t)(n0 + r0) * Hd + (k0) + c0;         \
        const __nv_bfloat16* sb1 = Bw + (size_t)(n0 + r1) * Hd + (k0) + c1;         \
        asm volatile("cp.async.cg.shared.global [%0], [%1], 16;\n" ::"r"(da0), "l"(sa0)); \
        asm volatile("cp.async.cg.shared.global [%0], [%1], 16;\n" ::"r"(da1), "l"(sa1)); \
        asm volatile("cp.async.cg.shared.global [%0], [%1], 16;\n" ::"r"(db0), "l"(sb0)); \
        asm volatile("cp.async.cg.shared.global [%0], [%1], 16;\n" ::"r"(db1), "l"(sb1)); \
    }

    LOAD_STAGE(0, 0)
    asm volatile("cp.async.commit_group;\n" ::: "memory");

    const int qm = lane >> 3, lr = lane & 7;

    int cur = 0;
#pragma unroll 1
    for (int k0 = 0; k0 < Hd; k0 += 32) {
        asm volatile("cp.async.wait_group 0;\n" ::: "memory");
        __syncthreads();
        if (k0 + 32 < Hd) {
            LOAD_STAGE(cur ^ 1, k0 + 32)
            asm volatile("cp.async.commit_group;\n" ::: "memory");
        }

#pragma unroll
        for (int ki = 0; ki < 2; ++ki) {
            const int kb = ki * 16;
            uint32_t af[4][4], bf[4][2];
#pragma unroll
            for (int mi = 0; mi < 4; mi++) {
                int rr = wm * 64 + mi * 16;
                uint32_t addr = sA + (uint32_t)(cur * 10240
                              + (rr + lr + (qm & 1) * 8) * 80
                              + (kb + (qm >> 1) * 8) * 2);
                asm volatile("ldmatrix.sync.aligned.m8n8.x4.shared.b16 {%0,%1,%2,%3}, [%4];"
                             : "=r"(af[mi][0]), "=r"(af[mi][1]), "=r"(af[mi][2]), "=r"(af[mi][3])
                             : "r"(addr));
            }
#pragma unroll
            for (int np = 0; np < 2; np++) {
                int nr = wn * 32 + np * 16;
                uint32_t addr = sB + (uint32_t)(cur * 10240
                              + (nr + lr + (qm >> 1) * 8) * 80
                              + (kb + (qm & 1) * 8) * 2);
                uint32_t t0, t1, t2, t3;
                asm volatile("ldmatrix.sync.aligned.m8n8.x4.shared.b16 {%0,%1,%2,%3}, [%4];"
                             : "=r"(t0), "=r"(t1), "=r"(t2), "=r"(t3)
                             : "r"(addr));
                bf[np * 2][0] = t0; bf[np * 2][1] = t1;
                bf[np * 2 + 1][0] = t2; bf[np * 2 + 1][1] = t3;
            }
#pragma unroll
            for (int mi = 0; mi < 4; mi++)
#pragma unroll
                for (int ni = 0; ni < 4; ni++)
                    mma16816bf(acc[mi][ni], af[mi], bf[ni]);
        }
        __syncthreads();
        cur ^= 1;
    }

#pragma unroll
    for (int mi = 0; mi < 4; mi++)
#pragma unroll
        for (int half = 0; half < 2; ++half) {
            int row = m0 + wm * 64 + mi * 16 + g + half * 8;
            if (row < Tt * Bb) {
                size_t orow = (size_t)(row & 63) * Tt + (row >> 6);
#pragma unroll
                for (int ni = 0; ni < 4; ni++) {
                    int col = n0 + wn * 32 + ni * 8 + 2 * tg;
                    float2 v;
                    v.x = acc[mi][ni][half * 2 + 0] + bias[col];
                    v.y = acc[mi][ni][half * 2 + 1] + bias[col + 1];
                    *(float2*)(out + orow * (size_t)Vv + col) = v;
                }
            }
        }
#undef LOAD_STAGE
}

// ---------------- log-softmax (blocks < 832) + h/c copy (blocks >= 832) ---
__global__ void __launch_bounds__(512)
lsm_copy(float* __restrict__ out)
{
    if (blockIdx.x >= Tt * Bb) {
        int base = (blockIdx.x - Tt * Bb) * 512 + threadIdx.x;
        for (int i = base; i < Bb * Hd; i += 16 * 512) {
            out[(size_t)Bb * Tt * Vv + i] = g_h[i];
            out[(size_t)Bb * Tt * Vv + (size_t)Bb * Hd + i] = g_c[i];
        }
        return;
    }
    const size_t bse = (size_t)blockIdx.x * Vv;
    const int tid = threadIdx.x;
    const int wid = tid >> 5, lane = tid & 31;
    __shared__ float rm[16], rs[16], fin[2];

    float m = -1e30f, s = 0.f;
    const float4* p = (const float4*)(out + bse);
    for (int i = tid; i < Vv / 4; i += 512) {
        float4 v = p[i];
        float xs[4] = {v.x, v.y, v.z, v.w};
#pragma unroll
        for (int e = 0; e < 4; e++) {
            float nm = fmaxf(m, xs[e]);
            s = s * __expf(m - nm) + __expf(xs[e] - nm);
            m = nm;
        }
    }
#pragma unroll
    for (int o = 16; o; o >>= 1) {
        float om = __shfl_xor_sync(0xffffffffu, m, o);
        float os = __shfl_xor_sync(0xffffffffu, s, o);
        float nm = fmaxf(m, om);
        s = s * __expf(m - nm) + os * __expf(om - nm);
        m = nm;
    }
    if (lane == 0) { rm[wid] = m; rs[wid] = s; }
    __syncthreads();
    if (wid == 0) {
        float mm = (lane < 16) ? rm[lane] : -1e30f;
        float ss = (lane < 16) ? rs[lane] : 0.f;
#pragma unroll
        for (int o = 8; o; o >>= 1) {
            float om = __shfl_xor_sync(0xffffffffu, mm, o);
            float os = __shfl_xor_sync(0xffffffffu, ss, o);
            float nm = fmaxf(mm, om);
            ss = ss * __expf(mm - nm) + os * __expf(om - nm);
            mm = nm;
        }
        if (lane == 0) { fin[0] = mm; fin[1] = ss; }
    }
    __syncthreads();
    float lse = fin[0] + logf(fin[1]);
    float4* q = (float4*)(out + bse);
    for (int i = tid; i < Vv / 4; i += 512) {
        float4 v = q[i];
        v.x -= lse; v.y -= lse; v.z -= lse; v.w -= lse;
        q[i] = v;
    }
}

// ---------------- launch ---------------------------------------------------
extern "C" void kernel_launch(void* const* d_in, const int* in_sizes, int n_in,
                              void* d_out, int out_size)
{
    (void)in_sizes; (void)n_in; (void)out_size;
    const float* enc    = (const float*)d_in[0];
    const float* enc_h  = (const float*)d_in[1];
    const float* enc_c  = (const float*)d_in[2];
    const int*   target = (const int*)  d_in[3];
    const float* emb    = (const float*)d_in[4];
    const float* Wa     = (const float*)d_in[5];
    const float* ba     = (const float*)d_in[6];
    const float* Ua     = (const float*)d_in[7];
    const float* bu     = (const float*)d_in[8];
    const float* Va     = (const float*)d_in[9];
    const float* bv     = (const float*)d_in[10];
    const float* W_ih   = (const float*)d_in[11];
    const float* W_hh   = (const float*)d_in[12];
    const float* b_ih   = (const float*)d_in[13];
    const float* b_hh   = (const float*)d_in[14];
    const float* ln_g   = (const float*)d_in[15];
    const float* ln_b   = (const float*)d_in[16];
    const float* outW   = (const float*)d_in[17];
    const float* outb   = (const float*)d_in[18];
    float* out = (float*)d_out;

    __nv_bfloat16 *nhb, *outWb;
    cudaGetSymbolAddress((void**)&nhb,   g_nhb);
    cudaGetSymbolAddress((void**)&outWb, g_outWb);

    float* out_attn = out + (size_t)Bb * Tt * Vv + 2 * (size_t)Bb * Hd;

    // (0) all conversions + embedding gather + state init, one launch
    prep_all<<<2048, 256>>>(W_hh, Wa, W_ih, Ua, enc, outW, emb, target,
                            enc_h, enc_c);
    // (1) xpre + keys(fp16), one launch
    pregemm<<<dim3(64, 1, 78), 128>>>(b_ih, b_hh, bu);

    for (int t = 0; t < Tt; t++) {
        hq_k<<<dim3(16, 4), 128>>>();                       // q partials
        scores_k<<<dim3(Bb, 8), 256>>>(Va, ba, bv);         // 512 blocks, 1 warp/score
        ctx_k<<<dim3(Bb, 4), 128>>>(out_attn, t);           // softmax + ctx (half2)
        hcgemm_k<<<dim3(128, 4), 128>>>();                  // h@Whh + ctx@Wc
        cell_k<<<Bb, 256>>>(ln_g, ln_b, t);                 // LSTM + LN
    }

    logits_gemm<<<dim3(Vv / 128, 7), 256>>>(nhb, outWb, outb, out);
    lsm_copy<<<Tt * Bb + 16, 512>>>(out);
}